// round 6
// baseline (speedup 1.0000x reference)
#include <cuda_runtime.h>
#include <stdint.h>

#define N_STRUCT   1000
#define ATOMS      100
#define N_SAMP     100000
#define N_GRAD     500000
#define DFEAT      128
#define NSEG       (N_STRUCT * ATOMS)      // 100000
#define ROW_F4     96                      // 3*128/4
#define GRAD_OUT_OFFSET (N_STRUCT * DFEAT)

#define CAP        64                      // bucket capacity (Poisson(5) max ~25)
#define BUILD_BLOCKS  ((N_GRAD + 255) / 256)   // 1954
#define VALUES_BLOCKS (N_STRUCT / 2)           // 500
#define GATHER_BLOCKS (NSEG / 8)               // 12500 (8 warps/block, 1 seg/warp)

// -------- scratch (device globals; zero-initialized at module load) --------
// g_count invariant: all-zero at entry to kernel_launch; gather restores it.
__device__ int g_count[NSEG];
__device__ int g_rows[NSEG * CAP];

// ---------------------------------------------------------------------------
// Kernel 1 (fused):
//   blocks [0, BUILD_BLOCKS): bucket build — one atomicAdd + one scattered
//     4B store per gradient row. No scan, no second pass.
//   blocks [BUILD_BLOCKS, +VALUES_BLOCKS): per-structure value sums
//     (structure_ids sorted -> binary search); overlaps the atomic-latency-
//     bound bucket build with bandwidth work.
// ---------------------------------------------------------------------------
__global__ void build_values_kernel(const int*   __restrict__ gstruct,
                                    const int*   __restrict__ gatom,
                                    const float* __restrict__ values,
                                    const int*   __restrict__ sid,
                                    float*       __restrict__ out) {
    if (blockIdx.x < BUILD_BLOCKS) {
        int i = blockIdx.x * 256 + threadIdx.x;
        if (i < N_GRAD) {
            int seg = gstruct[i] * ATOMS + gatom[i];
            int pos = atomicAdd(&g_count[seg], 1);
            if (pos < CAP) g_rows[seg * CAP + pos] = i;
        }
    } else {
        int vb   = blockIdx.x - BUILD_BLOCKS;
        int half = threadIdx.x >> 7;            // 0 or 1
        int d    = threadIdx.x & 127;
        int s    = vb * 2 + half;

        __shared__ int s_lo[2], s_hi[2];
        if (d == 0) {
            int lo = 0, hi = N_SAMP;
            while (lo < hi) { int m = (lo + hi) >> 1; if (sid[m] < s) lo = m + 1; else hi = m; }
            s_lo[half] = lo;
            lo = s_lo[half]; hi = N_SAMP;
            while (lo < hi) { int m = (lo + hi) >> 1; if (sid[m] < s + 1) lo = m + 1; else hi = m; }
            s_hi[half] = lo;
        }
        __syncthreads();

        float acc = 0.f;
        int lo = s_lo[half], hi = s_hi[half];
        for (int r = lo; r < hi; ++r)
            acc += values[(long long)r * DFEAT + d];
        __stcs(out + (long long)s * DFEAT + d, acc);
    }
}

// ---------------------------------------------------------------------------
// Kernel 2: gather-reduce, one warp per segment. Row ids prefetched into lane
// registers and shfl-broadcast -> every source load address-ready immediately
// (MLP ~= 3*cnt per warp). Streams 3x512B per row, writes 1536B once (.cs).
// Re-zeros g_count (restores invariant). Empty segments write zeros.
// ---------------------------------------------------------------------------
__global__ void gather_kernel(const float4* __restrict__ grad4,
                              float*        __restrict__ out_grad) {
    int warp_id = (blockIdx.x * 256 + threadIdx.x) >> 5;
    int lane    = threadIdx.x & 31;

    int cnt = g_count[warp_id];
    if (lane == 0) g_count[warp_id] = 0;    // restore invariant
    if (cnt > CAP) cnt = CAP;               // (never hit for this input)

    const int* bucket = g_rows + warp_id * CAP;
    int rid = (lane < cnt) ? bucket[lane] : 0;

    float4 a0 = make_float4(0.f, 0.f, 0.f, 0.f);
    float4 a1 = a0, a2 = a0;

    int n32 = cnt < 32 ? cnt : 32;
    #pragma unroll 4
    for (int p = 0; p < n32; ++p) {
        long long row = __shfl_sync(0xffffffffu, rid, p);
        const float4* src = grad4 + row * ROW_F4;
        float4 v0 = __ldcs(src + lane);
        float4 v1 = __ldcs(src + lane + 32);
        float4 v2 = __ldcs(src + lane + 64);
        a0.x += v0.x; a0.y += v0.y; a0.z += v0.z; a0.w += v0.w;
        a1.x += v1.x; a1.y += v1.y; a1.z += v1.z; a1.w += v1.w;
        a2.x += v2.x; a2.y += v2.y; a2.z += v2.z; a2.w += v2.w;
    }
    for (int p = 32; p < cnt; ++p) {        // overflow tail (never hit here)
        long long row = bucket[p];
        const float4* src = grad4 + row * ROW_F4;
        float4 v0 = __ldcs(src + lane);
        float4 v1 = __ldcs(src + lane + 32);
        float4 v2 = __ldcs(src + lane + 64);
        a0.x += v0.x; a0.y += v0.y; a0.z += v0.z; a0.w += v0.w;
        a1.x += v1.x; a1.y += v1.y; a1.z += v1.z; a1.w += v1.w;
        a2.x += v2.x; a2.y += v2.y; a2.z += v2.z; a2.w += v2.w;
    }

    float4* dst = (float4*)(out_grad + (long long)warp_id * (3 * DFEAT));
    __stcs(dst + lane,      a0);
    __stcs(dst + lane + 32, a1);
    __stcs(dst + lane + 64, a2);
}

// ---------------------------------------------------------------------------
extern "C" void kernel_launch(void* const* d_in, const int* in_sizes, int n_in,
                              void* d_out, int out_size) {
    const float*  values  = (const float*)d_in[0];
    const int*    sid     = (const int*)  d_in[1];
    const float4* grad4   = (const float4*)d_in[2];
    const int*    gstruct = (const int*)  d_in[3];
    const int*    gatom   = (const int*)  d_in[4];

    float* out      = (float*)d_out;
    float* out_grad = out + GRAD_OUT_OFFSET;

    build_values_kernel<<<BUILD_BLOCKS + VALUES_BLOCKS, 256>>>(
        gstruct, gatom, values, sid, out);

    gather_kernel<<<GATHER_BLOCKS, 256>>>(grad4, out_grad);
}

// round 7
// speedup vs baseline: 1.5150x; 1.5150x over previous
#include <cuda_runtime.h>
#include <stdint.h>

#define N_STRUCT   1000
#define ATOMS      100
#define N_SAMP     100000
#define N_GRAD     500000
#define DFEAT      128
#define NSEG       (N_STRUCT * ATOMS)      // 100000
#define ROW_F4     96                      // 3*128/4
#define GRAD_OUT_OFFSET (N_STRUCT * DFEAT)

#define SCAN_TILE  1024
#define SCAN_NB    ((NSEG + SCAN_TILE - 1) / SCAN_TILE)   // 98

#define COUNT_BLOCKS  ((N_GRAD + 255) / 256)   // 1954
#define VALUES_BLOCKS (N_STRUCT / 2)           // 500
#define GATHER_BLOCKS (NSEG / 8)               // 12500 (8 warps/block, 1 seg/warp)

// -------- scratch (device globals; zero-initialized at module load) --------
__device__ int g_count[NSEG];     // invariant: all-zero at kernel_launch entry
__device__ int g_start[NSEG + 1];
__device__ int g_cursor[NSEG];
__device__ int g_rows[N_GRAD];
__device__ int g_seg[N_GRAD];
__device__ int g_bsum[SCAN_NB];   // invariant: all-zero at entry (0 == not ready)

// ---------------------------------------------------------------------------
// Kernel 1 (fused): degree count (+seg cache) overlapped with values sums.
// ---------------------------------------------------------------------------
__global__ void count_values_kernel(const int*   __restrict__ gstruct,
                                    const int*   __restrict__ gatom,
                                    const float* __restrict__ values,
                                    const int*   __restrict__ sid,
                                    float*       __restrict__ out) {
    if (blockIdx.x < COUNT_BLOCKS) {
        int i = blockIdx.x * 256 + threadIdx.x;
        if (i < N_GRAD) {
            int seg = gstruct[i] * ATOMS + gatom[i];
            g_seg[i] = seg;
            atomicAdd(&g_count[seg], 1);
        }
    } else {
        // values segment-sum: 2 structures per block (sorted ids -> bsearch)
        int vb   = blockIdx.x - COUNT_BLOCKS;
        int half = threadIdx.x >> 7;
        int d    = threadIdx.x & 127;
        int s    = vb * 2 + half;

        __shared__ int s_lo[2], s_hi[2];
        if (d == 0) {
            int lo = 0, hi = N_SAMP;
            while (lo < hi) { int m = (lo + hi) >> 1; if (sid[m] < s) lo = m + 1; else hi = m; }
            s_lo[half] = lo;
            lo = s_lo[half]; hi = N_SAMP;
            while (lo < hi) { int m = (lo + hi) >> 1; if (sid[m] < s + 1) lo = m + 1; else hi = m; }
            s_hi[half] = lo;
        }
        __syncthreads();

        float acc = 0.f;
        int lo = s_lo[half], hi = s_hi[half];
        for (int r = lo; r < hi; ++r)
            acc += values[(long long)r * DFEAT + d];
        __stcs(out + (long long)s * DFEAT + d, acc);
    }
}

// ---------------------------------------------------------------------------
// Kernel 2: single-launch scan. Each of the 98 blocks scans its 1024-segment
// tile, publishes (tile_sum + 1) to g_bsum[b] (value doubles as ready flag),
// and warp 0 spin-accumulates the exclusive prefix over blocks j < b.
// All 98 blocks are co-resident (98 < 148 SMs) -> no deadlock.
// ---------------------------------------------------------------------------
__global__ void scan_kernel() {
    __shared__ int sh[SCAN_TILE];
    __shared__ int s_boff;
    int b = blockIdx.x;
    int i = b * SCAN_TILE + threadIdx.x;

    int v = (i < NSEG) ? g_count[i] : 0;
    sh[threadIdx.x] = v;
    __syncthreads();
    // Hillis-Steele inclusive scan
    for (int off = 1; off < SCAN_TILE; off <<= 1) {
        int t = (threadIdx.x >= off) ? sh[threadIdx.x - off] : 0;
        __syncthreads();
        sh[threadIdx.x] += t;
        __syncthreads();
    }

    // publish tile total (+1 so 0 means "not ready")
    if (threadIdx.x == SCAN_TILE - 1) {
        volatile int* p = g_bsum;
        p[b] = sh[SCAN_TILE - 1] + 1;
    }

    // warp 0: exclusive block offset via spin-lookback over j < b
    if (threadIdx.x < 32) {
        int acc = 0;
        volatile int* p = g_bsum;
        for (int j = (int)threadIdx.x; j < b; j += 32) {
            int w;
            while ((w = p[j]) == 0) { }
            acc += w - 1;
        }
        #pragma unroll
        for (int off = 16; off > 0; off >>= 1)
            acc += __shfl_down_sync(0xffffffffu, acc, off);
        if (threadIdx.x == 0) s_boff = acc;
    }
    __syncthreads();

    if (i < NSEG) {
        int excl = sh[threadIdx.x] - v + s_boff;
        g_start[i]  = excl;
        g_cursor[i] = excl;
    }
    if (i == NSEG - 1) g_start[NSEG] = N_GRAD;
}

// ---------------------------------------------------------------------------
// Kernel 3: scatter row ids into CSR lists; also restores g_bsum == 0.
// ---------------------------------------------------------------------------
__global__ void scatter_kernel() {
    int i = blockIdx.x * blockDim.x + threadIdx.x;
    if (blockIdx.x == 0 && threadIdx.x < SCAN_NB) g_bsum[threadIdx.x] = 0;
    if (i < N_GRAD) {
        int pos = atomicAdd(&g_cursor[g_seg[i]], 1);
        g_rows[pos] = i;
    }
}

// ---------------------------------------------------------------------------
// Kernel 4: gather-reduce (exact R4 hot path). One warp per segment; row ids
// prefetched into lanes + shfl broadcast -> all loads address-ready (high MLP).
// Re-zeros g_count. Empty segments write zeros.
// ---------------------------------------------------------------------------
__global__ void gather_kernel(const float4* __restrict__ grad4,
                              float*        __restrict__ out_grad) {
    // restore g_count == 0 invariant (cheap, overlapped)
    int zi = blockIdx.x * 256 + threadIdx.x;
    if (zi < NSEG) g_count[zi] = 0;

    int warp_id = (blockIdx.x * 256 + threadIdx.x) >> 5;
    int lane    = threadIdx.x & 31;

    int lo  = g_start[warp_id];
    int hi  = g_start[warp_id + 1];
    int cnt = hi - lo;

    // prefetch up to 32 row ids (Poisson(5): cnt>32 essentially never)
    int rid = (lane < cnt) ? g_rows[lo + lane] : 0;

    float4 a0 = make_float4(0.f, 0.f, 0.f, 0.f);
    float4 a1 = a0, a2 = a0;

    int n32 = cnt < 32 ? cnt : 32;
    #pragma unroll 4
    for (int p = 0; p < n32; ++p) {
        long long row = __shfl_sync(0xffffffffu, rid, p);
        const float4* src = grad4 + row * ROW_F4;
        float4 v0 = __ldcs(src + lane);
        float4 v1 = __ldcs(src + lane + 32);
        float4 v2 = __ldcs(src + lane + 64);
        a0.x += v0.x; a0.y += v0.y; a0.z += v0.z; a0.w += v0.w;
        a1.x += v1.x; a1.y += v1.y; a1.z += v1.z; a1.w += v1.w;
        a2.x += v2.x; a2.y += v2.y; a2.z += v2.z; a2.w += v2.w;
    }
    for (int p = 32; p < cnt; ++p) {    // overflow fallback (never hit here)
        long long row = g_rows[lo + p];
        const float4* src = grad4 + row * ROW_F4;
        float4 v0 = __ldcs(src + lane);
        float4 v1 = __ldcs(src + lane + 32);
        float4 v2 = __ldcs(src + lane + 64);
        a0.x += v0.x; a0.y += v0.y; a0.z += v0.z; a0.w += v0.w;
        a1.x += v1.x; a1.y += v1.y; a1.z += v1.z; a1.w += v1.w;
        a2.x += v2.x; a2.y += v2.y; a2.z += v2.z; a2.w += v2.w;
    }

    float4* dst = (float4*)(out_grad + (long long)warp_id * (3 * DFEAT));
    __stcs(dst + lane,      a0);
    __stcs(dst + lane + 32, a1);
    __stcs(dst + lane + 64, a2);
}

// ---------------------------------------------------------------------------
extern "C" void kernel_launch(void* const* d_in, const int* in_sizes, int n_in,
                              void* d_out, int out_size) {
    const float*  values  = (const float*)d_in[0];
    const int*    sid     = (const int*)  d_in[1];
    const float4* grad4   = (const float4*)d_in[2];
    const int*    gstruct = (const int*)  d_in[3];
    const int*    gatom   = (const int*)  d_in[4];

    float* out      = (float*)d_out;
    float* out_grad = out + GRAD_OUT_OFFSET;

    count_values_kernel<<<COUNT_BLOCKS + VALUES_BLOCKS, 256>>>(
        gstruct, gatom, values, sid, out);
    scan_kernel<<<SCAN_NB, SCAN_TILE>>>();
    scatter_kernel<<<(N_GRAD + 255) / 256, 256>>>();
    gather_kernel<<<GATHER_BLOCKS, 256>>>(grad4, out_grad);
}